// round 2
// baseline (speedup 1.0000x reference)
#include <cuda_runtime.h>
#include <math.h>

#define BSZ       512
#define NODES     1000
#define DIM       128
#define NB_HEADS  8
#define EMB3      384          // DIM * 3 layers, row stride of K_att / V_att
#define LSTR      1001         // smem stride -> conflict-free per-head writes

// Intermediate query buffers (device scratch; allocation-free per harness rules)
__device__ float g_q[2][BSZ * DIM];

// ---------------------------------------------------------------------------
// Decode the mask row for batch b into smask[0..NODES). The harness marshals
// the reference's bool array with an undocumented width; detect it from the
// first 1024 bytes (values are only 0/1, so the byte pattern is unambiguous).
// ---------------------------------------------------------------------------
__device__ __forceinline__ void load_mask_row(const void* mask, int b, int tid,
                                              unsigned char* smask)
{
    const unsigned char* p = (const unsigned char*)mask;
    bool viol_i32 = false, viol_f32 = false;
    if (tid < 256) {
        unsigned char b0 = p[4 * tid + 0];
        unsigned char b1 = p[4 * tid + 1];
        unsigned char b2 = p[4 * tid + 2];
        unsigned char b3 = p[4 * tid + 3];
        viol_i32 = (b1 | b2 | b3) != 0;
        bool zero = (b0 | b1 | b2 | b3) == 0;
        bool one  = (b0 == 0 && b1 == 0 && b2 == 0x80 && b3 == 0x3f);
        viol_f32 = !(zero || one);
    }
    const int any_i32_viol = __syncthreads_or(viol_i32);
    const int any_f32_viol = __syncthreads_or(viol_f32);

    if (!any_i32_viol) {                    // int32 0/1
        const int* mi = (const int*)mask + (size_t)b * NODES;
        for (int n = tid; n < NODES; n += blockDim.x)
            smask[n] = (mi[n] != 0);
    } else if (!any_f32_viol) {             // float32 0.0/1.0
        const float* mf = (const float*)mask + (size_t)b * NODES;
        for (int n = tid; n < NODES; n += blockDim.x)
            smask[n] = (mf[n] != 0.0f);
    } else {                                // uint8 0/1
        const unsigned char* mu = (const unsigned char*)mask + (size_t)b * NODES;
        for (int n = tid; n < NODES; n += blockDim.x)
            smask[n] = (mu[n] != 0);
    }
    __syncthreads();
}

// ---------------------------------------------------------------------------
// Layers 0 and 1: 8-head MHA over 1000 nodes + fused 128x128 linear (W0)
// One block per batch row. 512 threads = 16 warps.
// ---------------------------------------------------------------------------
__global__ __launch_bounds__(512, 3)
void attn_layer01(const float* __restrict__ K_att,
                  const float* __restrict__ V_att,
                  const void*  __restrict__ mask,
                  const float* __restrict__ query0,
                  const float* __restrict__ W0w,
                  const float* __restrict__ W0b,
                  int layer)
{
    __shared__ __align__(16) float sq[DIM];
    __shared__ float slog[NB_HEADS * LSTR];   // logits -> exp weights (32 KB)
    __shared__ float sinv[NB_HEADS];
    __shared__ float spart[4][DIM];
    __shared__ float sout[DIM];
    __shared__ unsigned char smask[NODES];

    const int b    = blockIdx.x;
    const int tid  = threadIdx.x;
    const int lane = tid & 31;
    const int warp = tid >> 5;

    load_mask_row(mask, b, tid, smask);

    const float* qin = (layer == 0) ? (query0 + b * DIM) : (g_q[0] + b * DIM);
    if (tid < DIM) sq[tid] = qin[tid];
    __syncthreads();

    const float4 q4 = reinterpret_cast<const float4*>(sq)[lane];
    const float* Kb = K_att + (size_t)b * NODES * EMB3 + layer * DIM;
    const float* Vb = V_att + (size_t)b * NODES * EMB3 + layer * DIM;

    // ---- Phase A: logits[h][n] for all heads -----------------------------
    for (int n0 = warp * 4; n0 < NODES; n0 += 64) {
        float4 k4[4];
        #pragma unroll
        for (int i = 0; i < 4; i++) {
            k4[i] = reinterpret_cast<const float4*>(Kb + (size_t)(n0 + i) * EMB3)[lane];
        }
        #pragma unroll
        for (int i = 0; i < 4; i++) {
            float p = k4[i].x * q4.x + k4[i].y * q4.y + k4[i].z * q4.z + k4[i].w * q4.w;
            p += __shfl_xor_sync(0xffffffffu, p, 1);
            p += __shfl_xor_sync(0xffffffffu, p, 2);
            if ((lane & 3) == 0) {
                const int n = n0 + i;
                const int h = lane >> 2;
                float lg = p * 0.25f;                 // 1/sqrt(16)
                if (smask[n]) lg = -1e9f;
                slog[h * LSTR + n] = lg;
            }
        }
    }
    __syncthreads();

    // ---- Per-head softmax: warp h owns head h ----------------------------
    if (warp < NB_HEADS) {
        float* L = slog + warp * LSTR;
        float m = -1e30f;
        for (int n = lane; n < NODES; n += 32) m = fmaxf(m, L[n]);
        #pragma unroll
        for (int o = 16; o; o >>= 1) m = fmaxf(m, __shfl_xor_sync(0xffffffffu, m, o));
        float s = 0.f;
        for (int n = lane; n < NODES; n += 32) {
            float e = __expf(L[n] - m);
            L[n] = e;
            s += e;
        }
        #pragma unroll
        for (int o = 16; o; o >>= 1) s += __shfl_xor_sync(0xffffffffu, s, o);
        if (lane == 0) sinv[warp] = 1.0f / s;
    }
    __syncthreads();

    // ---- Phase B: out[d] = (1/s_h) * sum_n e[h][n] * V[n][d] --------------
    {
        const int g = tid >> 7;          // group 0..3
        const int d = tid & 127;
        const int h = d >> 4;
        const float* Lh = slog + h * LSTR;
        float acc = 0.f;
        #pragma unroll 8
        for (int n = g; n < NODES; n += 4) {
            acc += Lh[n] * __ldg(Vb + (size_t)n * EMB3 + d);
        }
        spart[g][d] = acc;
    }
    __syncthreads();
    if (tid < DIM) {
        sout[tid] = (spart[0][tid] + spart[1][tid] + spart[2][tid] + spart[3][tid])
                    * sinv[tid >> 4];
    }
    __syncthreads();

    // ---- Fused linear: q_next = out @ W0w^T + W0b -------------------------
    if (tid < DIM) {
        float r = W0b[tid];
        const float* Wr = W0w + tid * DIM;
        #pragma unroll 8
        for (int k = 0; k < DIM; k++) r += Wr[k] * sout[k];
        g_q[layer][b * DIM + tid] = r;
    }
}

// ---------------------------------------------------------------------------
// Final layer: q = Wq q + b ; single-head logits with 10*tanh clip, mask,
// softmax over 1000 nodes -> output probabilities (512, 1000).
// ---------------------------------------------------------------------------
__global__ __launch_bounds__(512, 3)
void attn_final(const float* __restrict__ K_att,
                const void*  __restrict__ mask,
                const float* __restrict__ Wqw,
                const float* __restrict__ Wqb,
                float* __restrict__ out)
{
    __shared__ __align__(16) float sqin[DIM];
    __shared__ __align__(16) float sq[DIM];
    __shared__ float slog[NODES];
    __shared__ float sredm[16];
    __shared__ float sreds[16];
    __shared__ unsigned char smask[NODES];

    const int b    = blockIdx.x;
    const int tid  = threadIdx.x;
    const int lane = tid & 31;
    const int warp = tid >> 5;

    load_mask_row(mask, b, tid, smask);

    if (tid < DIM) sqin[tid] = g_q[1][b * DIM + tid];
    __syncthreads();
    if (tid < DIM) {
        float r = Wqb[tid];
        const float* Wr = Wqw + tid * DIM;
        #pragma unroll 8
        for (int k = 0; k < DIM; k++) r += Wr[k] * sqin[k];
        sq[tid] = r;
    }
    __syncthreads();

    const float4 q4 = reinterpret_cast<const float4*>(sq)[lane];
    const float* Kb = K_att + (size_t)b * NODES * EMB3 + 2 * DIM;
    const float scale = 0.0883883476483184f;   // 1/sqrt(128)

    for (int n0 = warp * 4; n0 < NODES; n0 += 64) {
        float4 k4[4];
        #pragma unroll
        for (int i = 0; i < 4; i++) {
            k4[i] = reinterpret_cast<const float4*>(Kb + (size_t)(n0 + i) * EMB3)[lane];
        }
        #pragma unroll
        for (int i = 0; i < 4; i++) {
            float p = k4[i].x * q4.x + k4[i].y * q4.y + k4[i].z * q4.z + k4[i].w * q4.w;
            #pragma unroll
            for (int o = 16; o; o >>= 1) p += __shfl_xor_sync(0xffffffffu, p, o);
            if (lane == 0) {
                const int n = n0 + i;
                float lg = 10.0f * tanhf(p * scale);
                if (smask[n]) lg = -1e9f;
                slog[n] = lg;
            }
        }
    }
    __syncthreads();

    // Block-wide max
    float m = -1e30f;
    for (int n = tid; n < NODES; n += 512) m = fmaxf(m, slog[n]);
    #pragma unroll
    for (int o = 16; o; o >>= 1) m = fmaxf(m, __shfl_xor_sync(0xffffffffu, m, o));
    if (lane == 0) sredm[warp] = m;
    __syncthreads();
    if (tid < 32) {
        float mm = (lane < 16) ? sredm[lane] : -1e30f;
        #pragma unroll
        for (int o = 8; o; o >>= 1) mm = fmaxf(mm, __shfl_xor_sync(0xffffffffu, mm, o));
        if (lane == 0) sredm[0] = mm;
    }
    __syncthreads();
    m = sredm[0];

    // exp + block-wide sum
    float s = 0.f;
    for (int n = tid; n < NODES; n += 512) {
        float e = __expf(slog[n] - m);
        slog[n] = e;
        s += e;
    }
    #pragma unroll
    for (int o = 16; o; o >>= 1) s += __shfl_xor_sync(0xffffffffu, s, o);
    if (lane == 0) sreds[warp] = s;
    __syncthreads();
    if (tid < 32) {
        float ss = (lane < 16) ? sreds[lane] : 0.f;
        #pragma unroll
        for (int o = 8; o; o >>= 1) ss += __shfl_xor_sync(0xffffffffu, ss, o);
        if (lane == 0) sreds[0] = ss;
    }
    __syncthreads();
    const float inv = 1.0f / sreds[0];

    float* ob = out + (size_t)b * NODES;
    for (int n = tid; n < NODES; n += 512) ob[n] = slog[n] * inv;
}

// ---------------------------------------------------------------------------
extern "C" void kernel_launch(void* const* d_in, const int* in_sizes, int n_in,
                              void* d_out, int out_size)
{
    const float* query = (const float*)d_in[0];
    const float* K_att = (const float*)d_in[1];
    const float* V_att = (const float*)d_in[2];
    const void*  mask  = d_in[3];
    const float* W0w   = (const float*)d_in[4];
    const float* W0b   = (const float*)d_in[5];
    const float* Wqw   = (const float*)d_in[6];
    const float* Wqb   = (const float*)d_in[7];
    float* out = (float*)d_out;

    attn_layer01<<<BSZ, 512>>>(K_att, V_att, mask, query, W0w, W0b, 0);
    attn_layer01<<<BSZ, 512>>>(K_att, V_att, mask, query, W0w, W0b, 1);
    attn_final  <<<BSZ, 512>>>(K_att, mask, Wqw, Wqb, out);
}

// round 3
// speedup vs baseline: 1.3851x; 1.3851x over previous
#include <cuda_runtime.h>
#include <math.h>

#define BSZ       512
#define NODES     1000
#define DIM       128
#define NB_HEADS  8
#define EMB3      384          // DIM * 3 layers, row stride of K_att / V_att
#define LSTR      1001         // smem stride -> conflict-free per-head access

// Intermediate query buffers (device scratch; allocation-free per harness rules)
__device__ float g_q[2][BSZ * DIM];

// ---------------------------------------------------------------------------
// Decode mask row for batch b into smask[0..NODES) with runtime layout
// detection (uint8 / int32 / float32), voted once per block.
// ---------------------------------------------------------------------------
__device__ __forceinline__ void load_mask_row(const void* mask, int b, int tid,
                                              unsigned char* smask)
{
    const unsigned char* p = (const unsigned char*)mask;
    bool viol_i32 = false, viol_f32 = false;
    if (tid < 256) {
        unsigned char b0 = p[4 * tid + 0];
        unsigned char b1 = p[4 * tid + 1];
        unsigned char b2 = p[4 * tid + 2];
        unsigned char b3 = p[4 * tid + 3];
        viol_i32 = (b1 | b2 | b3) != 0;
        bool zero = (b0 | b1 | b2 | b3) == 0;
        bool one  = (b0 == 0 && b1 == 0 && b2 == 0x80 && b3 == 0x3f);
        viol_f32 = !(zero || one);
    }
    const int any_i32_viol = __syncthreads_or(viol_i32);
    const int any_f32_viol = __syncthreads_or(viol_f32);

    if (!any_i32_viol) {
        const int* mi = (const int*)mask + (size_t)b * NODES;
        for (int n = tid; n < NODES; n += blockDim.x) smask[n] = (mi[n] != 0);
    } else if (!any_f32_viol) {
        const float* mf = (const float*)mask + (size_t)b * NODES;
        for (int n = tid; n < NODES; n += blockDim.x) smask[n] = (mf[n] != 0.0f);
    } else {
        const unsigned char* mu = (const unsigned char*)mask + (size_t)b * NODES;
        for (int n = tid; n < NODES; n += blockDim.x) smask[n] = (mu[n] != 0);
    }
    __syncthreads();
}

// ---------------------------------------------------------------------------
// Layers 0 and 1: 8-head MHA + fused 128x128 linear (W0).
// One block per batch row, 512 threads = 16 warps, 4 blocks/SM (single wave).
// ---------------------------------------------------------------------------
__global__ __launch_bounds__(512, 4)
void attn_layer01(const float* __restrict__ K_att,
                  const float* __restrict__ V_att,
                  const void*  __restrict__ mask,
                  const float* __restrict__ query0,
                  const float* __restrict__ W0w,
                  const float* __restrict__ W0b,
                  int layer)
{
    __shared__ __align__(16) float sq[DIM];
    __shared__ float slog[NB_HEADS * LSTR];    // logits -> exp weights (32 KB)
    __shared__ float sinv[NB_HEADS];
    __shared__ __align__(16) float spart[16][DIM];  // per-warp V partials (8 KB)
    __shared__ float sout[DIM];
    __shared__ float sredm[16], sreds[16];
    __shared__ unsigned char smask[NODES];

    const int b    = blockIdx.x;
    const int tid  = threadIdx.x;
    const int lane = tid & 31;
    const int warp = tid >> 5;

    load_mask_row(mask, b, tid, smask);

    const float* qin = (layer == 0) ? (query0 + b * DIM) : (g_q[0] + b * DIM);
    if (tid < DIM) sq[tid] = qin[tid];
    __syncthreads();

    const float4 q4 = reinterpret_cast<const float4*>(sq)[lane];
    const float* Kb = K_att + (size_t)b * NODES * EMB3 + layer * DIM;
    const float* Vb = V_att + (size_t)b * NODES * EMB3 + layer * DIM;

    // ---- Phase A: logits[h][n] (warp-per-node, 2-node unroll) -------------
    for (int n0 = warp * 2; n0 < NODES; n0 += 32) {
        float4 k0 = __ldg(reinterpret_cast<const float4*>(Kb + (size_t)n0 * EMB3) + lane);
        float4 k1 = __ldg(reinterpret_cast<const float4*>(Kb + (size_t)(n0 + 1) * EMB3) + lane);
        #pragma unroll
        for (int i = 0; i < 2; i++) {
            float4 k4 = i ? k1 : k0;
            float p = k4.x * q4.x + k4.y * q4.y + k4.z * q4.z + k4.w * q4.w;
            p += __shfl_xor_sync(0xffffffffu, p, 1);
            p += __shfl_xor_sync(0xffffffffu, p, 2);
            if ((lane & 3) == 0) {
                const int n = n0 + i;
                float lg = p * 0.25f;                 // 1/sqrt(16)
                if (smask[n]) lg = -1e9f;
                slog[(lane >> 2) * LSTR + n] = lg;
            }
        }
    }
    __syncthreads();

    // ---- Softmax: two warps per head (each takes half the nodes) ----------
    {
        const int h    = warp >> 1;
        const int half = warp & 1;
        float* L = slog + h * LSTR;
        float m = -1e30f;
        for (int n = half * 32 + lane; n < NODES; n += 64) m = fmaxf(m, L[n]);
        #pragma unroll
        for (int o = 16; o; o >>= 1) m = fmaxf(m, __shfl_xor_sync(0xffffffffu, m, o));
        if (lane == 0) sredm[warp] = m;
    }
    __syncthreads();
    {
        const int h    = warp >> 1;
        const int half = warp & 1;
        const float m  = fmaxf(sredm[2 * h], sredm[2 * h + 1]);
        float* L = slog + h * LSTR;
        float s = 0.f;
        for (int n = half * 32 + lane; n < NODES; n += 64) {
            float e = __expf(L[n] - m);
            L[n] = e;
            s += e;
        }
        #pragma unroll
        for (int o = 16; o; o >>= 1) s += __shfl_xor_sync(0xffffffffu, s, o);
        if (lane == 0) sreds[warp] = s;
    }
    __syncthreads();
    if (tid < NB_HEADS) sinv[tid] = 1.0f / (sreds[2 * tid] + sreds[2 * tid + 1]);

    // ---- Phase B: warp-per-node float4 accumulation -----------------------
    {
        const float* Lh = slog + (lane >> 2) * LSTR;
        float4 acc = make_float4(0.f, 0.f, 0.f, 0.f);
        int n = warp;
        for (; n + 16 < NODES; n += 32) {
            float4 v0 = __ldg(reinterpret_cast<const float4*>(Vb + (size_t)n * EMB3) + lane);
            float4 v1 = __ldg(reinterpret_cast<const float4*>(Vb + (size_t)(n + 16) * EMB3) + lane);
            float w0 = Lh[n];
            float w1 = Lh[n + 16];
            acc.x += w0 * v0.x; acc.y += w0 * v0.y; acc.z += w0 * v0.z; acc.w += w0 * v0.w;
            acc.x += w1 * v1.x; acc.y += w1 * v1.y; acc.z += w1 * v1.z; acc.w += w1 * v1.w;
        }
        for (; n < NODES; n += 16) {
            float4 v0 = __ldg(reinterpret_cast<const float4*>(Vb + (size_t)n * EMB3) + lane);
            float w0 = Lh[n];
            acc.x += w0 * v0.x; acc.y += w0 * v0.y; acc.z += w0 * v0.z; acc.w += w0 * v0.w;
        }
        reinterpret_cast<float4*>(spart[warp])[lane] = acc;
    }
    __syncthreads();
    if (tid < DIM) {
        float r = 0.f;
        #pragma unroll
        for (int w = 0; w < 16; w++) r += spart[w][tid];
        sout[tid] = r * sinv[tid >> 4];
    }
    __syncthreads();

    // ---- Fused linear: q_next = out @ W0w^T + W0b -------------------------
    if (tid < DIM) {
        float r = W0b[tid];
        const float* Wr = W0w + tid * DIM;
        #pragma unroll 8
        for (int k = 0; k < DIM; k++) r += Wr[k] * sout[k];
        g_q[layer][b * DIM + tid] = r;
    }
}

// ---------------------------------------------------------------------------
// Final layer: q = Wq q + b ; single-head logits with 10*tanh clip, mask,
// softmax over 1000 nodes -> output probabilities (512, 1000).
// Hot loop uses 2-shuffle partial reduction; 8 partials summed in SMEM pass.
// ---------------------------------------------------------------------------
__global__ __launch_bounds__(512, 4)
void attn_final(const float* __restrict__ K_att,
                const void*  __restrict__ mask,
                const float* __restrict__ Wqw,
                const float* __restrict__ Wqb,
                float* __restrict__ out)
{
    __shared__ __align__(16) float sqin[DIM];
    __shared__ __align__(16) float sq[DIM];
    __shared__ float spartl[8 * LSTR];   // per-16-dim-group logit partials (32 KB)
    __shared__ float slog[NODES];
    __shared__ float sredm[16], sreds[16];
    __shared__ unsigned char smask[NODES];

    const int b    = blockIdx.x;
    const int tid  = threadIdx.x;
    const int lane = tid & 31;
    const int warp = tid >> 5;

    load_mask_row(mask, b, tid, smask);

    if (tid < DIM) sqin[tid] = g_q[1][b * DIM + tid];
    __syncthreads();
    if (tid < DIM) {
        float r = Wqb[tid];
        const float* Wr = Wqw + tid * DIM;
        #pragma unroll 8
        for (int k = 0; k < DIM; k++) r += Wr[k] * sqin[k];
        sq[tid] = r;
    }
    __syncthreads();

    const float4 q4 = reinterpret_cast<const float4*>(sq)[lane];
    const float* Kb = K_att + (size_t)b * NODES * EMB3 + 2 * DIM;

    // Hot loop: K stream + 2-shuffle partials
    for (int n0 = warp * 2; n0 < NODES; n0 += 32) {
        float4 k0 = __ldg(reinterpret_cast<const float4*>(Kb + (size_t)n0 * EMB3) + lane);
        float4 k1 = __ldg(reinterpret_cast<const float4*>(Kb + (size_t)(n0 + 1) * EMB3) + lane);
        #pragma unroll
        for (int i = 0; i < 2; i++) {
            float4 k4 = i ? k1 : k0;
            float p = k4.x * q4.x + k4.y * q4.y + k4.z * q4.z + k4.w * q4.w;
            p += __shfl_xor_sync(0xffffffffu, p, 1);
            p += __shfl_xor_sync(0xffffffffu, p, 2);
            if ((lane & 3) == 0) {
                spartl[(lane >> 2) * LSTR + (n0 + i)] = p;
            }
        }
    }
    __syncthreads();

    // Combine partials -> logits (clip + mask)
    const float scale = 0.0883883476483184f;   // 1/sqrt(128)
    for (int n = tid; n < NODES; n += 512) {
        float s = 0.f;
        #pragma unroll
        for (int h = 0; h < 8; h++) s += spartl[h * LSTR + n];
        float lg = 10.0f * tanhf(s * scale);
        if (smask[n]) lg = -1e9f;
        slog[n] = lg;
    }
    __syncthreads();

    // Block-wide max
    float m = -1e30f;
    for (int n = tid; n < NODES; n += 512) m = fmaxf(m, slog[n]);
    #pragma unroll
    for (int o = 16; o; o >>= 1) m = fmaxf(m, __shfl_xor_sync(0xffffffffu, m, o));
    if (lane == 0) sredm[warp] = m;
    __syncthreads();
    if (tid < 32) {
        float mm = (lane < 16) ? sredm[lane] : -1e30f;
        #pragma unroll
        for (int o = 8; o; o >>= 1) mm = fmaxf(mm, __shfl_xor_sync(0xffffffffu, mm, o));
        if (lane == 0) sredm[0] = mm;
    }
    __syncthreads();
    m = sredm[0];

    // exp + block-wide sum
    float s = 0.f;
    for (int n = tid; n < NODES; n += 512) {
        float e = __expf(slog[n] - m);
        slog[n] = e;
        s += e;
    }
    #pragma unroll
    for (int o = 16; o; o >>= 1) s += __shfl_xor_sync(0xffffffffu, s, o);
    if (lane == 0) sreds[warp] = s;
    __syncthreads();
    if (tid < 32) {
        float ss = (lane < 16) ? sreds[lane] : 0.f;
        #pragma unroll
        for (int o = 8; o; o >>= 1) ss += __shfl_xor_sync(0xffffffffu, ss, o);
        if (lane == 0) sreds[0] = ss;
    }
    __syncthreads();
    const float inv = 1.0f / sreds[0];

    float* ob = out + (size_t)b * NODES;
    for (int n = tid; n < NODES; n += 512) ob[n] = slog[n] * inv;
}

// ---------------------------------------------------------------------------
extern "C" void kernel_launch(void* const* d_in, const int* in_sizes, int n_in,
                              void* d_out, int out_size)
{
    const float* query = (const float*)d_in[0];
    const float* K_att = (const float*)d_in[1];
    const float* V_att = (const float*)d_in[2];
    const void*  mask  = d_in[3];
    const float* W0w   = (const float*)d_in[4];
    const float* W0b   = (const float*)d_in[5];
    const float* Wqw   = (const float*)d_in[6];
    const float* Wqb   = (const float*)d_in[7];
    float* out = (float*)d_out;

    attn_layer01<<<BSZ, 512>>>(K_att, V_att, mask, query, W0w, W0b, 0);
    attn_layer01<<<BSZ, 512>>>(K_att, V_att, mask, query, W0w, W0b, 1);
    attn_final  <<<BSZ, 512>>>(K_att, mask, Wqw, Wqb, out);
}